// round 5
// baseline (speedup 1.0000x reference)
#include <cuda_runtime.h>
#include <math.h>

#define NB 4096
#define ND 128
#define ROWS 4
#define NTHREADS 256
#define MAXM 128
#define MARGINF 0.2f

__device__ double g_accum;
__device__ float g_sq[NB];

// Kernel 0: per-row squared norms + zero the global accumulator.
__global__ void sq_kernel(const float* __restrict__ X) {
    if (blockIdx.x == 0 && threadIdx.x == 0) g_accum = 0.0;
    int row = blockIdx.x * 8 + (threadIdx.x >> 5);
    int lane = threadIdx.x & 31;
    const float4* xv = (const float4*)(X + (size_t)row * ND);
    float4 v = xv[lane];            // 32 lanes x float4 = 128 floats
    float s = v.x * v.x + v.y * v.y + v.z * v.z + v.w * v.w;
    #pragma unroll
    for (int o = 16; o; o >>= 1) s += __shfl_xor_sync(0xffffffffu, s, o);
    if (lane == 0) g_sq[row] = s;
}

// Main kernel: ROWS query rows per CTA.
__global__ __launch_bounds__(NTHREADS, 3)
void rank_margin_kernel(const float* __restrict__ X, const int* __restrict__ labels) {
    extern __shared__ char smem_raw[];
    float*    sim    = (float*)smem_raw;                    // ROWS * NB
    float*    xs     = sim + ROWS * NB;                     // ROWS * ND
    unsigned* mmask  = (unsigned*)(xs + ROWS * ND);         // ROWS * NB/32
    float*    vm     = (float*)(mmask + ROWS * (NB / 32));  // MAXM
    int*      jm     = (int*)(vm + MAXM);                   // MAXM
    int*      cnt    = jm + MAXM;                           // MAXM
    float*    sqi    = (float*)(cnt + MAXM);                // ROWS
    int*      lbl    = (int*)(sqi + ROWS);                  // ROWS
    float*    rv     = (float*)(lbl + ROWS);                // 8
    int*      ri     = (int*)(rv + 8);                      // 8
    int*      mcount = ri + 8;                              // 1
    float*    wval   = (float*)(mcount + 1);                // 1
    int*      widx   = (int*)(wval + 1);                    // 1

    const float NEG_INF = __int_as_float(0xff800000);
    int tid = threadIdx.x;
    int lane = tid & 31;
    int wid = tid >> 5;
    int rowBase = blockIdx.x * ROWS;

    // Load query rows + their norms + labels into shared.
    for (int t = tid; t < ROWS * ND; t += NTHREADS)
        xs[t] = X[(size_t)rowBase * ND + t];
    if (tid < ROWS) {
        sqi[tid] = g_sq[rowBase + tid];
        lbl[tid] = labels[rowBase + tid];
    }
    __syncthreads();

    // ---------------- Phase A: sim rows ----------------
    const float4* xs4 = (const float4*)xs;
    for (int j = tid; j < NB; j += NTHREADS) {
        const float4* xj = (const float4*)(X + (size_t)j * ND);
        float a0 = 0.f, a1 = 0.f, a2 = 0.f, a3 = 0.f;
        #pragma unroll
        for (int c = 0; c < ND / 4; c++) {
            float4 v  = xj[c];
            float4 w0 = xs4[c];
            float4 w1 = xs4[32 + c];
            float4 w2 = xs4[64 + c];
            float4 w3 = xs4[96 + c];
            a0 += v.x * w0.x + v.y * w0.y + v.z * w0.z + v.w * w0.w;
            a1 += v.x * w1.x + v.y * w1.y + v.z * w1.z + v.w * w1.w;
            a2 += v.x * w2.x + v.y * w2.y + v.z * w2.z + v.w * w2.w;
            a3 += v.x * w3.x + v.y * w3.y + v.z * w3.z + v.w * w3.w;
        }
        float sqj = g_sq[j];
        int jl = labels[j];
        float acc[4] = {a0, a1, a2, a3};
        #pragma unroll
        for (int r = 0; r < ROWS; r++) {
            float d2 = fmaxf(sqi[r] + sqj - 2.0f * acc[r], 0.0f);
            bool match = (jl == lbl[r]);
            float s = (d2 == 0.0f) ? 0.0f : -sqrtf(d2);
            if (!match) s += MARGINF;
            sim[r * NB + j] = s;
            unsigned bal = __ballot_sync(0xffffffffu, match);
            if (lane == 0) mmask[r * (NB / 32) + (j >> 5)] = bal;
        }
    }
    __syncthreads();

    // ---------------- Phase B: per-row selection ----------------
    double block_total = 0.0;  // meaningful on tid 0 only
    for (int r = 0; r < ROWS; r++) {
        float* simr = sim + r * NB;
        unsigned* mk = mmask + r * (NB / 32);

        if (tid == 0) *mcount = 0;
        __syncthreads();

        // Cache this thread's 16 sims in registers; gather match list.
        float ls[16];
        #pragma unroll
        for (int t = 0; t < 16; t++) ls[t] = simr[tid + (t << 8)];
        #pragma unroll
        for (int t = 0; t < 16; t++) {
            int j = tid + (t << 8);
            if ((mk[j >> 5] >> (j & 31)) & 1u) {
                int p = atomicAdd(mcount, 1);
                if (p < MAXM) { jm[p] = j; vm[p] = ls[t]; cnt[p] = 0; }
            }
        }
        __syncthreads();
        int k = *mcount;
        if (k > MAXM) k = MAXM;

        // Count-based ranks for the matched elements (rank = cnt+1).
        for (int m = 0; m < k; m++) {
            float vmv = vm[m];
            int jmi = jm[m];
            int c = 0;
            #pragma unroll
            for (int t = 0; t < 16; t++) {
                int l = tid + (t << 8);
                float v = ls[t];
                c += (v > vmv || (v == vmv && l < jmi)) ? 1 : 0;
            }
            #pragma unroll
            for (int o = 16; o; o >>= 1) c += __shfl_xor_sync(0xffffffffu, c, o);
            if (lane == 0) atomicAdd(&cnt[m], c);
        }
        __syncthreads();

        // Extract top-k (stable tie-break: smaller index wins); e is the rank.
        float fp_acc = 0.f;  // thread 0 only
        float kf = (float)k;
        for (int e = 1; e <= k; e++) {
            float bv = NEG_INF;
            int bi = 1 << 30;
            #pragma unroll
            for (int t = 0; t < 16; t++) {
                int l = tid + (t << 8);
                float v = ls[t];
                if (v > bv || (v == bv && l < bi)) { bv = v; bi = l; }
            }
            #pragma unroll
            for (int o = 16; o; o >>= 1) {
                float ov = __shfl_xor_sync(0xffffffffu, bv, o);
                int oi = __shfl_xor_sync(0xffffffffu, bi, o);
                if (ov > bv || (ov == bv && oi < bi)) { bv = ov; bi = oi; }
            }
            if (lane == 0) { rv[wid] = bv; ri[wid] = bi; }
            __syncthreads();
            if (tid == 0) {
                float wv = rv[0]; int wi = ri[0];
                #pragma unroll
                for (int w = 1; w < 8; w++) {
                    if (rv[w] > wv || (rv[w] == wv && ri[w] < wi)) { wv = rv[w]; wi = ri[w]; }
                }
                *wval = wv; *widx = wi;
                if (!((mk[wi >> 5] >> (wi & 31)) & 1u)) {
                    // false positive at rank e
                    fp_acc += wv * (0.5f + (kf - (float)e + 1.0f) / kf * 0.5f);
                }
            }
            __syncthreads();
            int wi = *widx;
            #pragma unroll
            for (int t = 0; t < 16; t++)
                if (tid + (t << 8) == wi) ls[t] = NEG_INF;
            __syncthreads();
        }

        if (tid == 0) {
            float fn_acc = 0.f;
            float nf = (float)NB;
            for (int m = 0; m < k; m++) {
                int rank = cnt[m] + 1;
                if (rank > k) {
                    fn_acc += vm[m] * (0.5f + ((float)rank - kf) / (nf - kf) * 0.5f);
                }
            }
            block_total += (double)(fp_acc - fn_acc);
        }
        __syncthreads();
    }

    if (tid == 0) atomicAdd(&g_accum, block_total);
}

__global__ void out_kernel(float* out) {
    out[0] = (float)g_accum;
}

extern "C" void kernel_launch(void* const* d_in, const int* in_sizes, int n_in,
                              void* d_out, int out_size) {
    const float* X = (const float*)d_in[0];
    const int* labels = (const int*)d_in[1];
    float* out = (float*)d_out;

    // shared: sim + xs + mmask + small arrays
    size_t shmem = (size_t)ROWS * NB * 4 + ROWS * ND * 4 + ROWS * (NB / 32) * 4
                 + MAXM * 12 + ROWS * 8 + 8 * 8 + 64;
    cudaFuncSetAttribute(rank_margin_kernel,
                         cudaFuncAttributeMaxDynamicSharedMemorySize, (int)shmem);

    sq_kernel<<<NB / 8, 256>>>(X);
    rank_margin_kernel<<<NB / ROWS, NTHREADS, shmem>>>(X, labels);
    out_kernel<<<1, 1>>>(out);
}

// round 7
// speedup vs baseline: 2.1726x; 2.1726x over previous
#include <cuda_runtime.h>
#include <math.h>

#define NB 4096
#define ND 128
#define ROWS 8
#define NT 512
#define MAXM 64
#define MARGINF 0.2f

__device__ double g_accum;
__device__ __align__(16) float g_sq[NB];
__device__ __align__(16) float g_XT[ND * NB];   // transposed X: [c][j]

// ---------- packed f32x2 helpers (sm_103a FFMA2 path) ----------
__device__ __forceinline__ unsigned long long pk2(float lo, float hi) {
    unsigned long long r;
    asm("mov.b64 %0, {%1, %2};" : "=l"(r) : "f"(lo), "f"(hi));
    return r;
}
__device__ __forceinline__ void fma2(unsigned long long& d, unsigned long long a,
                                     unsigned long long b) {
    asm("fma.rn.f32x2 %0, %1, %2, %0;" : "+l"(d) : "l"(a), "l"(b));
}
__device__ __forceinline__ float2 upk2(unsigned long long v) {
    float2 r;
    asm("mov.b64 {%0, %1}, %2;" : "=f"(r.x), "=f"(r.y) : "l"(v));
    return r;
}

// Prep: squared norms + transpose + zero accumulator.
__global__ void prep_kernel(const float* __restrict__ X) {
    if (blockIdx.x == 0 && threadIdx.x == 0) g_accum = 0.0;
    int row = blockIdx.x * 8 + (threadIdx.x >> 5);
    int lane = threadIdx.x & 31;
    float4 v = ((const float4*)(X + (size_t)row * ND))[lane];
    float s = v.x * v.x + v.y * v.y + v.z * v.z + v.w * v.w;
    #pragma unroll
    for (int o = 16; o; o >>= 1) s += __shfl_xor_sync(0xffffffffu, s, o);
    if (lane == 0) g_sq[row] = s;
    int c = 4 * lane;
    g_XT[(c + 0) * NB + row] = v.x;
    g_XT[(c + 1) * NB + row] = v.y;
    g_XT[(c + 2) * NB + row] = v.z;
    g_XT[(c + 3) * NB + row] = v.w;
}

__device__ __forceinline__ float mksim(float si, float sj, float dot, bool mt) {
    float d2 = fmaxf(si + sj - 2.0f * dot, 0.0f);
    float s = (d2 == 0.0f) ? 0.0f : -sqrtf(d2);
    return mt ? s : s + MARGINF;
}

__global__ __launch_bounds__(NT, 1)
void rank_margin_kernel(const float* __restrict__ X, const int* __restrict__ labels) {
    extern __shared__ char smraw[];
    float*              simsh = (float*)smraw;                         // ROWS*NB
    unsigned long long* xsd   = (unsigned long long*)(simsh + ROWS * NB); // ND*ROWS dup pairs
    float* sqi    = (float*)(xsd + ND * ROWS);                         // ROWS
    int*   lbl    = (int*)(sqi + ROWS);                                // ROWS
    float* vm     = (float*)(lbl + ROWS);                              // MAXM
    int*   jm     = (int*)(vm + MAXM);                                 // MAXM
    int*   cnt    = jm + MAXM;                                         // MAXM
    float* rv     = (float*)(cnt + MAXM);                              // 16
    int*   ri     = (int*)(rv + 16);                                   // 16
    int*   rm     = ri + 16;                                           // 16
    int*   mcount = rm + 16;                                           // 1
    int*   widx   = mcount + 1;                                        // 1

    const float NEG_INF = __int_as_float(0xff800000);
    int tid = threadIdx.x;
    int lane = tid & 31;
    int wid = tid >> 5;
    int rowBase = blockIdx.x * ROWS;

    // Setup: duplicated query scalars xsd[c*8+r] = (x, x), norms, labels.
    for (int t = tid; t < ROWS * ND; t += NT) {
        int r = t & 7, c = t >> 3;
        float val = X[(size_t)(rowBase + r) * ND + c];
        xsd[t] = pk2(val, val);
    }
    if (tid < ROWS) {
        sqi[tid] = g_sq[rowBase + tid];
        lbl[tid] = labels[rowBase + tid];
    }
    __syncthreads();

    unsigned long long mbits = 0ull;  // match bit per (row, local-j)

    // ---------------- Phase A: Gram via packed FFMA2, coalesced XT loads ------
    #pragma unroll
    for (int t = 0; t < 2; t++) {
        unsigned long long acc[ROWS][2];
        #pragma unroll
        for (int r = 0; r < ROWS; r++) { acc[r][0] = 0ull; acc[r][1] = 0ull; }
        int col = tid + 512 * t;  // float4 column index within an XT row
        const float4* xt4 = (const float4*)g_XT;
        #pragma unroll 8
        for (int c = 0; c < ND; c++) {
            float4 v = xt4[c * (NB / 4) + col];          // coalesced, 4 j's
            unsigned long long vxy = pk2(v.x, v.y);
            unsigned long long vzw = pk2(v.z, v.w);
            const ulonglong2* xp = (const ulonglong2*)(xsd + c * 8);
            ulonglong2 x01 = xp[0], x23 = xp[1], x45 = xp[2], x67 = xp[3];
            fma2(acc[0][0], vxy, x01.x); fma2(acc[0][1], vzw, x01.x);
            fma2(acc[1][0], vxy, x01.y); fma2(acc[1][1], vzw, x01.y);
            fma2(acc[2][0], vxy, x23.x); fma2(acc[2][1], vzw, x23.x);
            fma2(acc[3][0], vxy, x23.y); fma2(acc[3][1], vzw, x23.y);
            fma2(acc[4][0], vxy, x45.x); fma2(acc[4][1], vzw, x45.x);
            fma2(acc[5][0], vxy, x45.y); fma2(acc[5][1], vzw, x45.y);
            fma2(acc[6][0], vxy, x67.x); fma2(acc[6][1], vzw, x67.x);
            fma2(acc[7][0], vxy, x67.y); fma2(acc[7][1], vzw, x67.y);
        }
        int jb = 4 * tid + 2048 * t;
        float4 sq4 = *(const float4*)(g_sq + jb);
        int4 lb4 = *(const int4*)(labels + jb);
        #pragma unroll
        for (int r = 0; r < ROWS; r++) {
            float2 a01 = upk2(acc[r][0]);
            float2 a23 = upk2(acc[r][1]);
            float si = sqi[r];
            int lr = lbl[r];
            bool m0 = (lb4.x == lr), m1 = (lb4.y == lr);
            bool m2 = (lb4.z == lr), m3 = (lb4.w == lr);
            float4 sv;
            sv.x = mksim(si, sq4.x, a01.x, m0);
            sv.y = mksim(si, sq4.y, a01.y, m1);
            sv.z = mksim(si, sq4.z, a23.x, m2);
            sv.w = mksim(si, sq4.w, a23.y, m3);
            int bb = r * 8 + t * 4;
            if (m0) mbits |= 1ull << (bb + 0);
            if (m1) mbits |= 1ull << (bb + 1);
            if (m2) mbits |= 1ull << (bb + 2);
            if (m3) mbits |= 1ull << (bb + 3);
            *(float4*)(simsh + r * NB + jb) = sv;
        }
    }
    __syncthreads();

    // ---------------- Phase B: per-row rank-aware selection --------------------
    double block_total = 0.0;  // meaningful on tid 0 only
    for (int r = 0; r < ROWS; r++) {
        const float* simr = simsh + r * NB;
        if (tid == 0) *mcount = 0;
        __syncthreads();

        // Register copy of this thread's 8 sims + global indices.
        float ls[8];
        int gj[8];
        #pragma unroll
        for (int t = 0; t < 2; t++) {
            int jb = 4 * tid + 2048 * t;
            float4 s4 = *(const float4*)(simr + jb);
            ls[t * 4 + 0] = s4.x; ls[t * 4 + 1] = s4.y;
            ls[t * 4 + 2] = s4.z; ls[t * 4 + 3] = s4.w;
            gj[t * 4 + 0] = jb + 0; gj[t * 4 + 1] = jb + 1;
            gj[t * 4 + 2] = jb + 2; gj[t * 4 + 3] = jb + 3;
        }
        unsigned mrow = (unsigned)(mbits >> (r * 8)) & 0xffu;

        // Gather matched elements.
        #pragma unroll
        for (int q = 0; q < 8; q++) {
            if ((mrow >> q) & 1u) {
                int p = atomicAdd(mcount, 1);
                if (p < MAXM) { jm[p] = gj[q]; vm[p] = ls[q]; cnt[p] = 0; }
            }
        }
        __syncthreads();
        int k = *mcount;
        if (k > MAXM) k = MAXM;

        // Count-based ranks of the matched elements (rank = cnt+1, stable ties).
        for (int m = 0; m < k; m++) {
            float vmv = vm[m];
            int jmi = jm[m];
            int c = 0;
            #pragma unroll
            for (int q = 0; q < 8; q++)
                c += (ls[q] > vmv || (ls[q] == vmv && gj[q] < jmi)) ? 1 : 0;
            c = __reduce_add_sync(0xffffffffu, c);
            if (lane == 0) atomicAdd(&cnt[m], c);
        }

        // Extract top-k (stable tie-break: smaller index wins); e is the rank.
        float kf = (float)k;
        float fp_acc = 0.0f;  // tid 0 only
        for (int e = 1; e <= k; e++) {
            float bv = NEG_INF;
            int bi = 1 << 30;
            int bm = 0;
            #pragma unroll
            for (int q = 0; q < 8; q++) {
                float v = ls[q];
                if (v > bv || (v == bv && gj[q] < bi)) {
                    bv = v; bi = gj[q]; bm = (mrow >> q) & 1;
                }
            }
            #pragma unroll
            for (int o = 16; o; o >>= 1) {
                float ov = __shfl_xor_sync(0xffffffffu, bv, o);
                int oi = __shfl_xor_sync(0xffffffffu, bi, o);
                int om = __shfl_xor_sync(0xffffffffu, bm, o);
                if (ov > bv || (ov == bv && oi < bi)) { bv = ov; bi = oi; bm = om; }
            }
            if (lane == 0) { rv[wid] = bv; ri[wid] = bi; rm[wid] = bm; }
            __syncthreads();
            if (tid == 0) {
                float wv = rv[0]; int wi2 = ri[0]; int wm = rm[0];
                #pragma unroll
                for (int w = 1; w < 16; w++)
                    if (rv[w] > wv || (rv[w] == wv && ri[w] < wi2)) {
                        wv = rv[w]; wi2 = ri[w]; wm = rm[w];
                    }
                *widx = wi2;
                if (!wm)  // false positive at rank e
                    fp_acc += wv * (0.5f + (kf - (float)e + 1.0f) / kf * 0.5f);
            }
            __syncthreads();
            int wi2 = *widx;
            #pragma unroll
            for (int q = 0; q < 8; q++)
                if (gj[q] == wi2) ls[q] = NEG_INF;
        }

        if (tid == 0) {
            float fn_acc = 0.0f;
            float nf = (float)NB;
            for (int m = 0; m < k; m++) {
                int rank = cnt[m] + 1;
                if (rank > k)
                    fn_acc += vm[m] * (0.5f + ((float)rank - kf) / (nf - kf) * 0.5f);
            }
            block_total += (double)(fp_acc - fn_acc);
        }
        // next-row mcount reset + barrier provides the needed ordering
    }

    if (tid == 0) atomicAdd(&g_accum, block_total);
}

__global__ void out_kernel(float* out) {
    out[0] = (float)g_accum;
}

extern "C" void kernel_launch(void* const* d_in, const int* in_sizes, int n_in,
                              void* d_out, int out_size) {
    const float* X = (const float*)d_in[0];
    const int* labels = (const int*)d_in[1];
    float* out = (float*)d_out;

    size_t shmem = (size_t)ROWS * NB * 4          // simsh
                 + (size_t)ND * ROWS * 8          // xsd dup pairs
                 + ROWS * 4 + ROWS * 4            // sqi, lbl
                 + MAXM * 12                      // vm, jm, cnt
                 + 16 * 12                        // rv, ri, rm
                 + 8;                             // mcount, widx
    cudaFuncSetAttribute(rank_margin_kernel,
                         cudaFuncAttributeMaxDynamicSharedMemorySize, (int)shmem);

    prep_kernel<<<NB / 8, 256>>>(X);
    rank_margin_kernel<<<NB / ROWS, NT, shmem>>>(X, labels);
    out_kernel<<<1, 1>>>(out);
}